// round 1
// baseline (speedup 1.0000x reference)
#include <cuda_runtime.h>

#define NB 16384
#define NKEY 64
#define ND 128
#define NU 128
#define NM 32
#define TB 128

// 2 MB scratch for softmax weights, stored transposed [mode][batch] for coalescing.
__device__ float g_sim[NM * NB];

// ---------------------------------------------------------------------------
// Kernel 1: sim[b,m] = softmax_m( sens[m] / (||key[b]-keys_map[m]|| + 1) ),
// pre-scaled by 1/MODES so the GEMM kernel needs no epilogue divide.
// ---------------------------------------------------------------------------
__global__ __launch_bounds__(128) void sim_kernel(const float* __restrict__ key,
                                                  const float* __restrict__ sens,
                                                  const float* __restrict__ keys_map)
{
    __shared__ float km[NM * NKEY];     // 8 KB
    __shared__ float ks[128 * 65];      // 33.3 KB, padded stride 65 (bank-conflict-free)
    __shared__ float ssens[NM];

    const int tid = threadIdx.x;
    const int row0 = blockIdx.x * 128;

    for (int i = tid; i < NM * NKEY; i += 128) km[i] = keys_map[i];
    if (tid < NM) ssens[tid] = sens[tid];
    for (int i = tid; i < 128 * NKEY; i += 128) {
        ks[(i >> 6) * 65 + (i & 63)] = key[row0 * NKEY + i];
    }
    __syncthreads();

    float lg[NM];
    float mx = -1e30f;
    const float* myk = &ks[tid * 65];
    for (int m = 0; m < NM; m++) {
        float d2 = 0.f;
        #pragma unroll
        for (int k = 0; k < NKEY; k++) {
            float df = myk[k] - km[m * NKEY + k];
            d2 = fmaf(df, df, d2);
        }
        float l = ssens[m] / (sqrtf(d2) + 1.0f);
        lg[m] = l;
        mx = fmaxf(mx, l);
    }
    float s = 0.f;
    for (int m = 0; m < NM; m++) { float e = expf(lg[m] - mx); lg[m] = e; s += e; }
    const float inv = 0.03125f / s;     // softmax normalize AND fold 1/MODES here
    const int b = row0 + tid;
    for (int m = 0; m < NM; m++) g_sim[m * NB + b] = lg[m] * inv;  // coalesced per m
}

// ---------------------------------------------------------------------------
// Packed f32x2 helpers (FFMA2: the only path to full fp32 rate on sm_103a).
// ---------------------------------------------------------------------------
__device__ __forceinline__ unsigned long long pack2(float v) {
    unsigned long long r;
    unsigned int u = __float_as_uint(v);
    asm("mov.b64 %0, {%1, %1};" : "=l"(r) : "r"(u));
    return r;
}
__device__ __forceinline__ void fma2(unsigned long long& d, unsigned long long a,
                                     unsigned long long b) {
    asm("fma.rn.f32x2 %0, %1, %2, %0;" : "+l"(d) : "l"(a), "l"(b));
}
__device__ __forceinline__ unsigned long long add2(unsigned long long a,
                                                   unsigned long long b) {
    unsigned long long r;
    asm("add.rn.f32x2 %0, %1, %2;" : "=l"(r) : "l"(a), "l"(b));
    return r;
}

// Dynamic SMEM layout (floats)
#define XS_STRIDE 132                       // pad: 132*4B % 16 == 0, 4-way-max store conflicts
#define SM_BS     (ND * XS_STRIDE)          // 16896
#define SM_SIMS   (SM_BS + 2 * 16 * NU)     // 20992  (double-buffered B chunks)
#define SM_BSS    (SM_SIMS + NM * TB)       // 25088
#define SM_FLOATS (SM_BSS + NM * NU)        // 29184
#define SMEM_BYTES (SM_FLOATS * 4)          // 116736 B

// ---------------------------------------------------------------------------
// Kernel 2: out[b,u] = sum_m sim'[b,m] * ( x[b,:] @ kernels[m,:,u] + biases[m,u] )
// (sim' already contains the 1/MODES factor.)
// Tile: 128 rows x 128 cols per block, 256 threads, 8x8 outputs/thread as f32x2.
// ---------------------------------------------------------------------------
__global__ __launch_bounds__(256, 1) void gemm_kernel(
    const float* __restrict__ x, const float* __restrict__ kernels,
    const float* __restrict__ biases, float* __restrict__ out)
{
    extern __shared__ float sm[];
    float* XsT  = sm;             // [d][row] transposed, stride 132
    float* Bs   = sm + SM_BS;     // [2][16][128]
    float* sims = sm + SM_SIMS;   // [32][128]
    float* bss  = sm + SM_BSS;    // [32][128]

    const int tid = threadIdx.x;
    const int tx = tid & 15;      // columns: tx*4..+3 and 64+tx*4..+3
    const int ty = tid >> 4;      // rows:    ty*8..+7
    const int row0 = blockIdx.x * TB;

    const float4* kg4 = (const float4*)kernels;   // chunk c = floats [c*2048, c*2048+2048)

    // Prefetch B chunk 0 early (hides LDG latency behind the tile loads below)
    float4 pf0 = kg4[tid];
    float4 pf1 = kg4[tid + 256];

    // x tile -> transposed SMEM
    {
        const float4* xg = (const float4*)(x + (size_t)row0 * ND);
        #pragma unroll
        for (int it = 0; it < (TB * ND / 4) / 256; it++) {
            int i = it * 256 + tid;
            float4 v = xg[i];
            int r = (i * 4) >> 7;
            int d = (i * 4) & 127;
            XsT[(d + 0) * XS_STRIDE + r] = v.x;
            XsT[(d + 1) * XS_STRIDE + r] = v.y;
            XsT[(d + 2) * XS_STRIDE + r] = v.z;
            XsT[(d + 3) * XS_STRIDE + r] = v.w;
        }
    }
    for (int i = tid; i < NM * TB; i += 256)
        sims[i] = g_sim[(i >> 7) * NB + row0 + (i & 127)];
    for (int i = tid; i < NM * NU; i += 256) bss[i] = biases[i];

    { // commit chunk 0
        float4* bd = (float4*)Bs;
        bd[tid] = pf0;
        bd[tid + 256] = pf1;
    }
    __syncthreads();

    unsigned long long acc[8][4];
    #pragma unroll
    for (int i = 0; i < 8; i++)
        #pragma unroll
        for (int j = 0; j < 4; j++) acc[i][j] = 0ULL;

    unsigned long long macc[8][4];
    unsigned long long sim2[8];
    unsigned long long bias2[4];

    int buf = 0;
    for (int c = 0; c < NM * 8; c++) {          // c = m*8 + kc  (256 chunks of K=16)
        const int kc = c & 7;

        // register-staged prefetch of next B chunk
        if (c + 1 < NM * 8) {
            pf0 = kg4[(c + 1) * 512 + tid];
            pf1 = kg4[(c + 1) * 512 + 256 + tid];
        }

        if (kc == 0) {
            const int m = c >> 3;
            #pragma unroll
            for (int i = 0; i < 8; i++)
                sim2[i] = pack2(sims[m * TB + ty * 8 + i]);
            const ulonglong2 t0 = *(const ulonglong2*)&bss[m * NU + tx * 4];
            const ulonglong2 t1 = *(const ulonglong2*)&bss[m * NU + 64 + tx * 4];
            bias2[0] = t0.x; bias2[1] = t0.y; bias2[2] = t1.x; bias2[3] = t1.y;
            #pragma unroll
            for (int i = 0; i < 8; i++)
                #pragma unroll
                for (int j = 0; j < 4; j++) macc[i][j] = 0ULL;
        }

        // 16 k-steps from current buffer
        const float* bbase = Bs + buf * (16 * NU);
        const int kb = kc * 16;
        #pragma unroll
        for (int k = 0; k < 16; k++) {
            const float* arow = &XsT[(kb + k) * XS_STRIDE + ty * 8];
            const float4 a0 = *(const float4*)(arow);
            const float4 a1 = *(const float4*)(arow + 4);
            const ulonglong2 b01 = *(const ulonglong2*)(bbase + k * NU + tx * 4);
            const ulonglong2 b23 = *(const ulonglong2*)(bbase + k * NU + 64 + tx * 4);
            const unsigned long long bb0 = b01.x, bb1 = b01.y, bb2 = b23.x, bb3 = b23.y;
            const float av[8] = {a0.x, a0.y, a0.z, a0.w, a1.x, a1.y, a1.z, a1.w};
            #pragma unroll
            for (int i = 0; i < 8; i++) {
                const unsigned long long ap = pack2(av[i]);
                fma2(macc[i][0], ap, bb0);
                fma2(macc[i][1], ap, bb1);
                fma2(macc[i][2], ap, bb2);
                fma2(macc[i][3], ap, bb3);
            }
        }

        // fold mode into the running accumulator: acc += sim * (macc + bias)
        if (kc == 7) {
            #pragma unroll
            for (int i = 0; i < 8; i++)
                #pragma unroll
                for (int j = 0; j < 4; j++)
                    fma2(acc[i][j], sim2[i], add2(macc[i][j], bias2[j]));
        }

        __syncthreads();
        if (c + 1 < NM * 8) {
            float4* bd = (float4*)(Bs + (buf ^ 1) * (16 * NU));
            bd[tid] = pf0;
            bd[tid + 256] = pf1;
        }
        __syncthreads();
        buf ^= 1;
    }

    // epilogue: acc already includes softmax-normalized 1/MODES scaling
    #pragma unroll
    for (int i = 0; i < 8; i++) {
        const int row = row0 + ty * 8 + i;
        ulonglong2 o0; o0.x = acc[i][0]; o0.y = acc[i][1];
        ulonglong2 o1; o1.x = acc[i][2]; o1.y = acc[i][3];
        *(ulonglong2*)(&out[(size_t)row * NU + tx * 4]) = o0;
        *(ulonglong2*)(&out[(size_t)row * NU + 64 + tx * 4]) = o1;
    }
}

// ---------------------------------------------------------------------------
extern "C" void kernel_launch(void* const* d_in, const int* in_sizes, int n_in,
                              void* d_out, int out_size)
{
    // All six inputs have distinct element counts -> bind by size (robust to order).
    const float *key = 0, *x = 0, *sens = 0, *keys_map = 0, *kernels = 0, *biases = 0;
    for (int i = 0; i < n_in; i++) {
        switch (in_sizes[i]) {
            case NB * NKEY:      key      = (const float*)d_in[i]; break;  // 1048576
            case NB * ND:        x        = (const float*)d_in[i]; break;  // 2097152
            case NM:             sens     = (const float*)d_in[i]; break;  // 32
            case NM * NKEY:      keys_map = (const float*)d_in[i]; break;  // 2048
            case NM * ND * NU:   kernels  = (const float*)d_in[i]; break;  // 524288
            case NM * NU:        biases   = (const float*)d_in[i]; break;  // 4096
            default: break;
        }
    }
    float* out = (float*)d_out;

    cudaFuncSetAttribute(gemm_kernel, cudaFuncAttributeMaxDynamicSharedMemorySize,
                         SMEM_BYTES);

    sim_kernel<<<NB / 128, 128>>>(key, sens, keys_map);
    gemm_kernel<<<NB / TB, 256, SMEM_BYTES>>>(x, kernels, biases, out);
}

// round 3
// speedup vs baseline: 3.5309x; 3.5309x over previous
#include <cuda_runtime.h>
#include <cuda_fp16.h>
#include <cstdint>

#define NB 16384
#define NKEY 64
#define ND 128
#define NU 128
#define NM 32
#define TB 128
#define NCH 33            // 32 weight chunks (K=128) + 1 bias chunk (K=32, zero-padded)
#define CHB 32768         // bytes per fragment-ordered fp16 B chunk (128k x 128n)

__device__ float g_sim[NM * NB];                       // unnormalized softmax, [m][b]
__device__ __align__(16) unsigned char g_Bf[NCH * CHB];

// ---------------------------------------------------------------------------
// Kernel 1: sim[b,m] = softmax_m( sens[m] / (dist + 1) )   (no 1/32 fold here)
// ---------------------------------------------------------------------------
__global__ __launch_bounds__(128) void sim_kernel(const float* __restrict__ key,
                                                  const float* __restrict__ sens,
                                                  const float* __restrict__ keys_map)
{
    __shared__ float km[NM * NKEY];
    __shared__ float ks[128 * 65];
    __shared__ float ssens[NM];

    const int tid = threadIdx.x;
    const int row0 = blockIdx.x * 128;

    for (int i = tid; i < NM * NKEY; i += 128) km[i] = keys_map[i];
    if (tid < NM) ssens[tid] = sens[tid];
    for (int i = tid; i < 128 * NKEY; i += 128)
        ks[(i >> 6) * 65 + (i & 63)] = key[row0 * NKEY + i];
    __syncthreads();

    float lg[NM];
    float mx = -1e30f;
    const float* myk = &ks[tid * 65];
    for (int m = 0; m < NM; m++) {
        float d2 = 0.f;
        #pragma unroll
        for (int k = 0; k < NKEY; k++) {
            float df = myk[k] - km[m * NKEY + k];
            d2 = fmaf(df, df, d2);
        }
        float l = ssens[m] / (sqrtf(d2) + 1.0f);
        lg[m] = l;
        mx = fmaxf(mx, l);
    }
    float s = 0.f;
    for (int m = 0; m < NM; m++) { float e = expf(lg[m] - mx); lg[m] = e; s += e; }
    const float inv = 1.0f / s;
    const int b = row0 + tid;
    for (int m = 0; m < NM; m++) g_sim[m * NB + b] = lg[m] * inv;
}

// ---------------------------------------------------------------------------
// Kernel 2: B chunks -> fp16 fragment order.
// Fragment (chunk c, kstep ks, nfrag nf, lane l{g=l>>2,t=l&3}) holds:
//   b0 = half2( B[k0][n], B[k0+1][n] ),  b1 = half2( B[k0+8][n], B[k0+9][n] )
// with k0 = 16*ks + 2*t, n = 8*nf + g.  Chunk c<32: B = kernels[c][k][n].
// Chunk 32: B = (k<32) ? biases[k][n] : 0.
// ---------------------------------------------------------------------------
__global__ __launch_bounds__(256) void prep_b(const float* __restrict__ kernels,
                                              const float* __restrict__ biases)
{
    __shared__ float Bk[128 * 129];
    const int c = blockIdx.x, tid = threadIdx.x;

    for (int i = tid; i < 128 * 128; i += 256) {
        const int k = i >> 7, n = i & 127;
        float v;
        if (c < 32) v = kernels[(size_t)c * 16384 + i];
        else        v = (k < 32) ? biases[k * 128 + n] : 0.f;
        Bk[k * 129 + n] = v;
    }
    __syncthreads();

    for (int fi = tid; fi < 4096; fi += 256) {
        const int l = fi & 31, nf = (fi >> 5) & 15, ksn = fi >> 9;
        const int g = l >> 2, t = l & 3;
        const int n = nf * 8 + g, k0 = ksn * 16 + 2 * t;
        __half2 h0 = __floats2half2_rn(Bk[k0 * 129 + n], Bk[(k0 + 1) * 129 + n]);
        __half2 h1 = __floats2half2_rn(Bk[(k0 + 8) * 129 + n], Bk[(k0 + 9) * 129 + n]);
        uint2 w;
        w.x = *(uint32_t*)&h0;
        w.y = *(uint32_t*)&h1;
        *(uint2*)(g_Bf + (size_t)c * CHB + (size_t)fi * 8) = w;
    }
}

// ---------------------------------------------------------------------------
// Kernel 3: fp16 mma.sync GEMM, 128 CTAs x 256 threads.
// CTA tile 128 rows x 128 cols; warp tile 32x64 (4 rowgroups x 2 colgroups).
// ---------------------------------------------------------------------------
#define XS_OFF  0                       // 128*132 f32  = 67584 B
#define SIM_OFF 67584                   // 128*36 f32   = 18432 B
#define A_OFF   86016                   // 2 x 32768
#define B_OFF   151552                  // 2 x 32768
#define SMEM_BYTES 217088

__device__ __forceinline__ void mma16816(float* c, const uint32_t* a,
                                         uint32_t b0, uint32_t b1) {
    asm volatile(
        "mma.sync.aligned.m16n8k16.row.col.f32.f16.f16.f32 "
        "{%0,%1,%2,%3}, {%4,%5,%6,%7}, {%8,%9}, {%0,%1,%2,%3};"
        : "+f"(c[0]), "+f"(c[1]), "+f"(c[2]), "+f"(c[3])
        : "r"(a[0]), "r"(a[1]), "r"(a[2]), "r"(a[3]), "r"(b0), "r"(b1));
}

__global__ __launch_bounds__(256, 1) void mma_kernel(const float* __restrict__ x,
                                                     float* __restrict__ out)
{
    extern __shared__ __align__(16) unsigned char sm[];
    float* Xs   = (float*)(sm + XS_OFF);     // [row][d], stride 132
    float* simS = (float*)(sm + SIM_OFF);    // [row][m], stride 36

    uint32_t smb;
    asm("{ .reg .u64 t; cvta.to.shared.u64 t, %1; cvt.u32.u64 %0, t; }"
        : "=r"(smb) : "l"(sm));
    uint64_t gb;
    {
        const unsigned char* p = g_Bf;
        asm("cvta.to.global.u64 %0, %1;" : "=l"(gb) : "l"(p));
    }

    const int tid = threadIdx.x;
    const int l = tid & 31, w = tid >> 5;
    const int rg = w >> 1, cg = w & 1;
    const int row0 = blockIdx.x * TB;

    // ---- issue cp.async for B chunk 0 ----
    {
        const uint32_t dst = smb + B_OFF;
        #pragma unroll
        for (int j = 0; j < 8; j++) {
            const uint32_t off = (uint32_t)(j * 256 + tid) * 16;
            asm volatile("cp.async.cg.shared.global [%0], [%1], 16;"
                         :: "r"(dst + off), "l"(gb + off));
        }
        asm volatile("cp.async.commit_group;");
    }

    // ---- load X tile (fp32) and sims into SMEM ----
    {
        const float4* xg = (const float4*)(x + (size_t)row0 * ND);
        #pragma unroll
        for (int it = 0; it < 16; it++) {
            const int idx = it * 256 + tid;           // float4 index, 4096 total
            float4 v = xg[idx];
            const int r = (idx * 4) >> 7, col = (idx * 4) & 127;
            *(float4*)&Xs[r * 132 + col] = v;
        }
        for (int i = tid; i < NM * TB; i += 256) {
            const int m = i >> 7, r = i & 127;
            simS[r * 36 + m] = g_sim[m * NB + row0 + r];
        }
    }
    __syncthreads();

    // ---- build A chunk 0 ----
    auto build_a = [&](int ch, unsigned char* dst) {
        const int g = l >> 2, t = l & 3;
        #pragma unroll
        for (int i = 0; i < 8; i++) {
            const int q = (tid >> 5) + 8 * i;         // 0..63 = rb*8+ks
            const int rb = q >> 3, ksn = q & 7;
            const int r0 = rb * 16 + g;
            const int k0 = ksn * 16 + 2 * t;
            uint4 frag;
            if (ch < 32) {
                const float s0 = simS[r0 * 36 + ch];
                const float s1 = simS[(r0 + 8) * 36 + ch];
                const float2 x00 = *(const float2*)&Xs[r0 * 132 + k0];
                const float2 x01 = *(const float2*)&Xs[r0 * 132 + k0 + 8];
                const float2 x10 = *(const float2*)&Xs[(r0 + 8) * 132 + k0];
                const float2 x11 = *(const float2*)&Xs[(r0 + 8) * 132 + k0 + 8];
                __half2 h0 = __floats2half2_rn(s0 * x00.x, s0 * x00.y);
                __half2 h1 = __floats2half2_rn(s1 * x10.x, s1 * x10.y);
                __half2 h2 = __floats2half2_rn(s0 * x01.x, s0 * x01.y);
                __half2 h3 = __floats2half2_rn(s1 * x11.x, s1 * x11.y);
                frag.x = *(uint32_t*)&h0;
                frag.y = *(uint32_t*)&h1;
                frag.z = *(uint32_t*)&h2;
                frag.w = *(uint32_t*)&h3;
            } else if (ksn < 2) {                     // bias chunk: A = sim, k<32
                const float2 s00 = *(const float2*)&simS[r0 * 36 + k0];
                const float2 s01 = *(const float2*)&simS[r0 * 36 + k0 + 8];
                const float2 s10 = *(const float2*)&simS[(r0 + 8) * 36 + k0];
                const float2 s11 = *(const float2*)&simS[(r0 + 8) * 36 + k0 + 8];
                __half2 h0 = __floats2half2_rn(s00.x, s00.y);
                __half2 h1 = __floats2half2_rn(s10.x, s10.y);
                __half2 h2 = __floats2half2_rn(s01.x, s01.y);
                __half2 h3 = __floats2half2_rn(s11.x, s11.y);
                frag.x = *(uint32_t*)&h0;
                frag.y = *(uint32_t*)&h1;
                frag.z = *(uint32_t*)&h2;
                frag.w = *(uint32_t*)&h3;
            } else {
                frag.x = frag.y = frag.z = frag.w = 0u;
            }
            *(uint4*)(dst + (size_t)(q * 32 + l) * 16) = frag;
        }
    };

    build_a(0, sm + A_OFF);
    asm volatile("cp.async.wait_group 0;");
    __syncthreads();

    float acc[2][8][4];
    #pragma unroll
    for (int mf = 0; mf < 2; mf++)
        #pragma unroll
        for (int nf = 0; nf < 8; nf++)
            #pragma unroll
            for (int i = 0; i < 4; i++) acc[mf][nf][i] = 0.f;

    for (int c = 0; c <= 32; c++) {
        const int cur = c & 1;
        // prefetch B chunk c+1 (buffer it will occupy was fully read in iter c-1)
        if (c + 1 <= 32) {
            const uint32_t dst = smb + B_OFF + (cur ^ 1) * 32768;
            const uint64_t src = gb + (uint64_t)(c + 1) * CHB;
            #pragma unroll
            for (int j = 0; j < 8; j++) {
                const uint32_t off = (uint32_t)(j * 256 + tid) * 16;
                asm volatile("cp.async.cg.shared.global [%0], [%1], 16;"
                             :: "r"(dst + off), "l"(src + off));
            }
            asm volatile("cp.async.commit_group;");
            build_a(c + 1, sm + A_OFF + (cur ^ 1) * 32768);
        }

        // MMA over chunk c
        const uint4* aab = (const uint4*)(sm + A_OFF + cur * 32768);
        const uint2* bbb = (const uint2*)(sm + B_OFF + cur * 32768);
        #pragma unroll
        for (int ksn = 0; ksn < 8; ksn++) {
            uint4 A0 = aab[((rg * 2 + 0) * 8 + ksn) * 32 + l];
            uint4 A1 = aab[((rg * 2 + 1) * 8 + ksn) * 32 + l];
            uint32_t a0[4] = {A0.x, A0.y, A0.z, A0.w};
            uint32_t a1[4] = {A1.x, A1.y, A1.z, A1.w};
            #pragma unroll
            for (int nf = 0; nf < 8; nf++) {
                uint2 B = bbb[(ksn * 16 + cg * 8 + nf) * 32 + l];
                mma16816(acc[0][nf], a0, B.x, B.y);
                mma16816(acc[1][nf], a1, B.x, B.y);
            }
        }

        asm volatile("cp.async.wait_group 0;");
        __syncthreads();
    }

    // ---- epilogue: scale by 1/32 and store ----
    const float sc = 1.0f / 32.0f;
    const int g = l >> 2, t = l & 3;
    #pragma unroll
    for (int mf = 0; mf < 2; mf++) {
        const int r = row0 + rg * 32 + mf * 16 + g;
        #pragma unroll
        for (int nf = 0; nf < 8; nf++) {
            const int col = cg * 64 + nf * 8 + 2 * t;
            float2 v0, v1;
            v0.x = acc[mf][nf][0] * sc; v0.y = acc[mf][nf][1] * sc;
            v1.x = acc[mf][nf][2] * sc; v1.y = acc[mf][nf][3] * sc;
            *(float2*)&out[(size_t)r * NU + col] = v0;
            *(float2*)&out[(size_t)(r + 8) * NU + col] = v1;
        }
    }
}

// ---------------------------------------------------------------------------
extern "C" void kernel_launch(void* const* d_in, const int* in_sizes, int n_in,
                              void* d_out, int out_size)
{
    const float *key = 0, *x = 0, *sens = 0, *keys_map = 0, *kernels = 0, *biases = 0;
    for (int i = 0; i < n_in; i++) {
        switch (in_sizes[i]) {
            case NB * NKEY:    key      = (const float*)d_in[i]; break;
            case NB * ND:      x        = (const float*)d_in[i]; break;
            case NM:           sens     = (const float*)d_in[i]; break;
            case NM * NKEY:    keys_map = (const float*)d_in[i]; break;
            case NM * ND * NU: kernels  = (const float*)d_in[i]; break;
            case NM * NU:      biases   = (const float*)d_in[i]; break;
            default: break;
        }
    }
    float* out = (float*)d_out;

    cudaFuncSetAttribute(mma_kernel, cudaFuncAttributeMaxDynamicSharedMemorySize,
                         SMEM_BYTES);

    sim_kernel<<<NB / 128, 128>>>(key, sens, keys_map);
    prep_b<<<NCH, 256>>>(kernels, biases);
    mma_kernel<<<NB / TB, 256, SMEM_BYTES>>>(x, out);
}

// round 4
// speedup vs baseline: 4.8703x; 1.3794x over previous
#include <cuda_runtime.h>
#include <cuda_fp16.h>
#include <cstdint>

#define NB 16384
#define NKEY 64
#define ND 128
#define NU 128
#define NM 32
#define TB 128
#define NCH 33            // 32 weight chunks (K=128) + 1 bias chunk (K=32, zero-padded)
#define CHB 32768         // bytes per fragment-ordered fp16 B chunk

#define SIM_BLOCKS 2048   // 8 rows each
#define PREP_BLOCKS 132   // 33 chunks x 4 parts

__device__ float g_sim[NB * NM];                       // [b][m], normalized softmax
__device__ __align__(16) unsigned char g_Bf[NCH * CHB];

// ---------------------------------------------------------------------------
// Fused prep kernel.
//   blocks [0, 2048): sim — warp per row, lane per mode.
//   blocks [2048, 2180): B chunks -> fp16 fragment order (chunk c = bid>>2, part p = bid&3).
// Fragment (chunk c, ksn, nf, lane l{g=l>>2,t=l&3}):
//   b0 = half2(B[k0][n], B[k0+1][n]), b1 = half2(B[k0+8][n], B[k0+9][n]),
//   k0 = 16*ksn + 2*t, n = 8*nf + g.  c<32: B=kernels[c][k][n]; c==32: B=(k<32)?biases[k][n]:0.
// ---------------------------------------------------------------------------
__global__ __launch_bounds__(256) void prep_kernel(const float* __restrict__ key,
                                                   const float* __restrict__ sens,
                                                   const float* __restrict__ keys_map,
                                                   const float* __restrict__ kernels,
                                                   const float* __restrict__ biases)
{
    __shared__ float sbuf[32 * 129];   // 16.5 KB, role-dependent layout
    const int bid = blockIdx.x, tid = threadIdx.x;

    if (bid < SIM_BLOCKS) {
        float* km = sbuf;              // [32][65] padded
        float* ks = sbuf + 2080;       // [8][64]
        float* ss = sbuf + 2592;       // [32]
        const int row0 = bid * 8;

        for (int i = tid; i < NM * NKEY; i += 256) km[(i >> 6) * 65 + (i & 63)] = keys_map[i];
        for (int i = tid; i < 8 * NKEY; i += 256) ks[i] = key[row0 * NKEY + i];
        if (tid < NM) ss[tid] = sens[tid];
        __syncthreads();

        const int w = tid >> 5, m = tid & 31;
        float d2 = 0.f;
        #pragma unroll
        for (int k = 0; k < NKEY; k++) {
            const float df = ks[w * NKEY + k] - km[m * 65 + k];
            d2 = fmaf(df, df, d2);
        }
        const float lg = ss[m] / (sqrtf(d2) + 1.0f);
        float mx = lg;
        #pragma unroll
        for (int o = 16; o > 0; o >>= 1) mx = fmaxf(mx, __shfl_xor_sync(0xFFFFFFFFu, mx, o));
        const float e = expf(lg - mx);
        float s = e;
        #pragma unroll
        for (int o = 16; o > 0; o >>= 1) s += __shfl_xor_sync(0xFFFFFFFFu, s, o);
        g_sim[(row0 + w) * NM + m] = e / s;
    } else {
        const int pb = bid - SIM_BLOCKS;
        const int c = pb >> 2, p = pb & 3;
        float* Bs = sbuf;              // [32][129] padded

        for (int i = tid; i < 32 * 128; i += 256) {
            const int kl = i >> 7, n = i & 127, k = p * 32 + kl;
            float v;
            if (c < 32) v = kernels[(size_t)c * 16384 + (size_t)k * 128 + n];
            else        v = (p == 0) ? biases[k * 128 + n] : 0.f;
            Bs[kl * 129 + n] = v;
        }
        __syncthreads();

        for (int j = tid; j < 1024; j += 256) {
            const int fi = p * 1024 + j;
            const int l = fi & 31, nf = (fi >> 5) & 15, ksn = fi >> 9;
            const int g = l >> 2, t = l & 3;
            const int n = nf * 8 + g;
            const int kl = ksn * 16 + 2 * t - p * 32;
            __half2 h0 = __floats2half2_rn(Bs[kl * 129 + n], Bs[(kl + 1) * 129 + n]);
            __half2 h1 = __floats2half2_rn(Bs[(kl + 8) * 129 + n], Bs[(kl + 9) * 129 + n]);
            uint2 wv;
            wv.x = *(uint32_t*)&h0;
            wv.y = *(uint32_t*)&h1;
            *(uint2*)(g_Bf + (size_t)c * CHB + (size_t)fi * 8) = wv;
        }
    }
}

// ---------------------------------------------------------------------------
// GEMM kernel: 128 CTAs x 512 threads (16 warps, warp tile 32x32).
// Thread owns 4 fixed A-fragment slots: rb = w>>1, ksn in [(w&1)*4, +4);
// its 32 x-values live in registers across all 33 chunks.
// ---------------------------------------------------------------------------
#define XS_OFF  0                       // 128*132 f32 = 67584 B (prologue only)
#define SIM_OFF 67584                   // 128*36 f32  = 18432 B
#define A_OFF   86016                   // 2 x 32768
#define B_OFF   151552                  // 2 x 32768
#define SMEM_BYTES 217088

__device__ __forceinline__ void mma16816(float* c, const uint32_t* a,
                                         uint32_t b0, uint32_t b1) {
    asm volatile(
        "mma.sync.aligned.m16n8k16.row.col.f32.f16.f16.f32 "
        "{%0,%1,%2,%3}, {%4,%5,%6,%7}, {%8,%9}, {%0,%1,%2,%3};"
        : "+f"(c[0]), "+f"(c[1]), "+f"(c[2]), "+f"(c[3])
        : "r"(a[0]), "r"(a[1]), "r"(a[2]), "r"(a[3]), "r"(b0), "r"(b1));
}

__global__ __launch_bounds__(512, 1) void mma_kernel(const float* __restrict__ x,
                                                     float* __restrict__ out)
{
    extern __shared__ __align__(16) unsigned char sm[];
    float* Xs   = (float*)(sm + XS_OFF);     // [row][d] stride 132
    float* simS = (float*)(sm + SIM_OFF);    // [row][m] stride 36

    uint32_t smb;
    asm("{ .reg .u64 t; cvta.to.shared.u64 t, %1; cvt.u32.u64 %0, t; }"
        : "=r"(smb) : "l"(sm));
    uint64_t gb;
    {
        const unsigned char* p = g_Bf;
        asm("cvta.to.global.u64 %0, %1;" : "=l"(gb) : "l"(p));
    }

    const int tid = threadIdx.x;
    const int l = tid & 31, w = tid >> 5;
    const int g = l >> 2, t = l & 3;
    const int rb = w >> 1, ksnb = (w & 1) * 4;       // A-build mapping
    const int rg = w >> 2, cg = w & 3;               // MMA mapping (32x32 warp tile)
    const int r0 = rb * 16 + g, r1 = r0 + 8;
    const int row0 = blockIdx.x * TB;

    // ---- cp.async B chunk 0 ----
    #pragma unroll
    for (int j = 0; j < 4; j++) {
        const uint32_t off = (uint32_t)(j * 512 + tid) * 16;
        asm volatile("cp.async.cg.shared.global [%0], [%1], 16;"
                     :: "r"(smb + B_OFF + off), "l"(gb + off));
    }
    asm volatile("cp.async.commit_group;");

    // ---- stage X (fp32) and sims ----
    {
        const float4* xg = (const float4*)(x + (size_t)row0 * ND);
        #pragma unroll
        for (int it = 0; it < 8; it++) {
            const int idx = it * 512 + tid;
            float4 v = xg[idx];
            const int r = (idx * 4) >> 7, col = (idx * 4) & 127;
            *(float4*)&Xs[r * 132 + col] = v;
        }
        for (int i = tid; i < NM * TB; i += 512) {
            const int r = i >> 5, m = i & 31;
            simS[r * 36 + m] = g_sim[(row0 + r) * NM + m];
        }
    }
    __syncthreads();

    // ---- cache this thread's 32 x-values in registers ----
    float xr[32];
    #pragma unroll
    for (int j = 0; j < 4; j++) {
        const int k0 = (ksnb + j) * 16 + 2 * t;
        float2 v;
        v = *(const float2*)&Xs[r0 * 132 + k0];     xr[j*8+0] = v.x; xr[j*8+1] = v.y;
        v = *(const float2*)&Xs[r0 * 132 + k0 + 8]; xr[j*8+2] = v.x; xr[j*8+3] = v.y;
        v = *(const float2*)&Xs[r1 * 132 + k0];     xr[j*8+4] = v.x; xr[j*8+5] = v.y;
        v = *(const float2*)&Xs[r1 * 132 + k0 + 8]; xr[j*8+6] = v.x; xr[j*8+7] = v.y;
    }

    auto build_a = [&](int ch, unsigned char* dst) {
        #pragma unroll
        for (int j = 0; j < 4; j++) {
            const int ksn = ksnb + j;
            const int q = rb * 8 + ksn;
            uint4 frag;
            if (ch < 32) {
                const float s0 = simS[r0 * 36 + ch];
                const float s1 = simS[r1 * 36 + ch];
                __half2 h0 = __floats2half2_rn(s0 * xr[j*8+0], s0 * xr[j*8+1]);
                __half2 h1 = __floats2half2_rn(s1 * xr[j*8+4], s1 * xr[j*8+5]);
                __half2 h2 = __floats2half2_rn(s0 * xr[j*8+2], s0 * xr[j*8+3]);
                __half2 h3 = __floats2half2_rn(s1 * xr[j*8+6], s1 * xr[j*8+7]);
                frag.x = *(uint32_t*)&h0; frag.y = *(uint32_t*)&h1;
                frag.z = *(uint32_t*)&h2; frag.w = *(uint32_t*)&h3;
            } else if (ksn < 2) {                  // bias chunk: A = sim, K=32
                const int k0 = ksn * 16 + 2 * t;
                const float2 a = *(const float2*)&simS[r0 * 36 + k0];
                const float2 b = *(const float2*)&simS[r0 * 36 + k0 + 8];
                const float2 cc = *(const float2*)&simS[r1 * 36 + k0];
                const float2 d = *(const float2*)&simS[r1 * 36 + k0 + 8];
                __half2 h0 = __floats2half2_rn(a.x, a.y);
                __half2 h1 = __floats2half2_rn(cc.x, cc.y);
                __half2 h2 = __floats2half2_rn(b.x, b.y);
                __half2 h3 = __floats2half2_rn(d.x, d.y);
                frag.x = *(uint32_t*)&h0; frag.y = *(uint32_t*)&h1;
                frag.z = *(uint32_t*)&h2; frag.w = *(uint32_t*)&h3;
            } else {
                frag.x = frag.y = frag.z = frag.w = 0u;
            }
            *(uint4*)(dst + (size_t)(q * 32 + l) * 16) = frag;
        }
    };

    build_a(0, sm + A_OFF);
    asm volatile("cp.async.wait_group 0;");
    __syncthreads();

    float acc[2][4][4];
    #pragma unroll
    for (int mf = 0; mf < 2; mf++)
        #pragma unroll
        for (int nf = 0; nf < 4; nf++)
            #pragma unroll
            for (int i = 0; i < 4; i++) acc[mf][nf][i] = 0.f;

    for (int c = 0; c <= 32; c++) {
        const int cur = c & 1;

        if (c < 32) {   // prefetch B chunk c+1
            const uint32_t dst = smb + B_OFF + (cur ^ 1) * 32768;
            const uint64_t src = gb + (uint64_t)(c + 1) * CHB;
            #pragma unroll
            for (int j = 0; j < 4; j++) {
                const uint32_t off = (uint32_t)(j * 512 + tid) * 16;
                asm volatile("cp.async.cg.shared.global [%0], [%1], 16;"
                             :: "r"(dst + off), "l"(src + off));
            }
            asm volatile("cp.async.commit_group;");
        }

        // MMA chunk c — feed the tensor pipe before doing conversion work
        const uint4* aab = (const uint4*)(sm + A_OFF + cur * 32768);
        const uint2* bbb = (const uint2*)(sm + B_OFF + cur * 32768);
        #pragma unroll
        for (int ksn = 0; ksn < 8; ksn++) {
            uint4 A0 = aab[((rg * 2 + 0) * 8 + ksn) * 32 + l];
            uint4 A1 = aab[((rg * 2 + 1) * 8 + ksn) * 32 + l];
            uint32_t a0[4] = {A0.x, A0.y, A0.z, A0.w};
            uint32_t a1[4] = {A1.x, A1.y, A1.z, A1.w};
            #pragma unroll
            for (int nf = 0; nf < 4; nf++) {
                uint2 B = bbb[(ksn * 16 + cg * 4 + nf) * 32 + l];
                mma16816(acc[0][nf], a0, B.x, B.y);
                mma16816(acc[1][nf], a1, B.x, B.y);
            }
        }

        if (c < 32) build_a(c + 1, sm + A_OFF + (cur ^ 1) * 32768);

        asm volatile("cp.async.wait_group 0;");
        __syncthreads();
    }

    // ---- epilogue: scale by 1/32, store ----
    const float sc = 1.0f / 32.0f;
    #pragma unroll
    for (int mf = 0; mf < 2; mf++) {
        const int r = row0 + rg * 32 + mf * 16 + g;
        #pragma unroll
        for (int nf = 0; nf < 4; nf++) {
            const int col = cg * 32 + nf * 8 + 2 * t;
            float2 v0, v1;
            v0.x = acc[mf][nf][0] * sc; v0.y = acc[mf][nf][1] * sc;
            v1.x = acc[mf][nf][2] * sc; v1.y = acc[mf][nf][3] * sc;
            *(float2*)&out[(size_t)r * NU + col] = v0;
            *(float2*)&out[(size_t)(r + 8) * NU + col] = v1;
        }
    }
}

// ---------------------------------------------------------------------------
extern "C" void kernel_launch(void* const* d_in, const int* in_sizes, int n_in,
                              void* d_out, int out_size)
{
    const float *key = 0, *x = 0, *sens = 0, *keys_map = 0, *kernels = 0, *biases = 0;
    for (int i = 0; i < n_in; i++) {
        switch (in_sizes[i]) {
            case NB * NKEY:    key      = (const float*)d_in[i]; break;
            case NB * ND:      x        = (const float*)d_in[i]; break;
            case NM:           sens     = (const float*)d_in[i]; break;
            case NM * NKEY:    keys_map = (const float*)d_in[i]; break;
            case NM * ND * NU: kernels  = (const float*)d_in[i]; break;
            case NM * NU:      biases   = (const float*)d_in[i]; break;
            default: break;
        }
    }
    float* out = (float*)d_out;

    cudaFuncSetAttribute(mma_kernel, cudaFuncAttributeMaxDynamicSharedMemorySize,
                         SMEM_BYTES);

    prep_kernel<<<SIM_BLOCKS + PREP_BLOCKS, 256>>>(key, sens, keys_map, kernels, biases);
    mma_kernel<<<NB / TB, 512, SMEM_BYTES>>>(x, out);
}

// round 5
// speedup vs baseline: 4.9875x; 1.0241x over previous
#include <cuda_runtime.h>
#include <cuda_fp16.h>
#include <cstdint>

#define NB 16384
#define NKEY 64
#define ND 128
#define NU 128
#define NM 32
#define TB 128
#define NCH 33            // 32 weight chunks (K=128) + 1 bias chunk (K=32, zero-padded)
#define CHB 32768         // bytes per fragment-ordered fp16 B chunk

__device__ __align__(16) unsigned char g_Bf[NCH * CHB];

// ---------------------------------------------------------------------------
// prep_b: B chunks -> fp16 fragment order with nf-PAIRED uint4 layout.
// uint4 at ((ksn*8 + jp)*32 + l)*16 holds, for lane l {g=l>>2, t=l&3},
// k0 = 16*ksn + 2*t, n_e = jp*16+g, n_o = n_e+8:
//   { h2(B[k0][n_e],B[k0+1][n_e]), h2(B[k0+8][n_e],B[k0+9][n_e]),
//     h2(B[k0][n_o],B[k0+1][n_o]), h2(B[k0+8][n_o],B[k0+9][n_o]) }
// c<32: B=kernels[c][k][n]; c==32: B=(k<32)?biases[k][n]:0.
// Grid: 33 chunks x 4 k-parts (32 rows each).
// ---------------------------------------------------------------------------
__global__ __launch_bounds__(256) void prep_b(const float* __restrict__ kernels,
                                              const float* __restrict__ biases)
{
    __shared__ float Bs[32 * 129];
    const int pb = blockIdx.x;
    const int c = pb >> 2, p = pb & 3;
    const int tid = threadIdx.x;

    for (int i = tid; i < 32 * 128; i += 256) {
        const int kl = i >> 7, n = i & 127, k = p * 32 + kl;
        float v;
        if (c < 32) v = kernels[(size_t)c * 16384 + (size_t)k * 128 + n];
        else        v = (p == 0) ? biases[k * 128 + n] : 0.f;
        Bs[kl * 129 + n] = v;
    }
    __syncthreads();

    #pragma unroll
    for (int it = 0; it < 2; it++) {
        const int i = it * 256 + tid;               // 512 uint4 per part
        const int ksn = 2 * p + (i >> 8);
        const int rest = i & 255;
        const int jp = rest >> 5, l = rest & 31;
        const int g = l >> 2, t = l & 3;
        const int kl = 16 * (i >> 8) + 2 * t;       // local k within part (0..31)
        const int ne = jp * 16 + g, no = ne + 8;
        __half2 h0 = __floats2half2_rn(Bs[kl * 129 + ne], Bs[(kl + 1) * 129 + ne]);
        __half2 h1 = __floats2half2_rn(Bs[(kl + 8) * 129 + ne], Bs[(kl + 9) * 129 + ne]);
        __half2 h2 = __floats2half2_rn(Bs[kl * 129 + no], Bs[(kl + 1) * 129 + no]);
        __half2 h3 = __floats2half2_rn(Bs[(kl + 8) * 129 + no], Bs[(kl + 9) * 129 + no]);
        uint4 wv;
        wv.x = *(uint32_t*)&h0; wv.y = *(uint32_t*)&h1;
        wv.z = *(uint32_t*)&h2; wv.w = *(uint32_t*)&h3;
        *(uint4*)(g_Bf + (size_t)c * CHB +
                  (size_t)(((ksn * 8 + jp) * 32 + l)) * 16) = wv;
    }
}

// ---------------------------------------------------------------------------
// mma_kernel: 128 CTAs x 256 threads (8 warps, warp tile 32x64).
// Prologue computes sim (softmax) for this CTA's 128 rows in-kernel.
// A: 2-stage SMEM double buffer built from registers (xr) + simS.
// B: 4-stage cp.async pipeline (depth-3 prefetch).
// ---------------------------------------------------------------------------
#define SIM_OFF 0                       // 128*33 f32 = 16896 B
#define A_OFF   16896                   // 2 x 32768
#define B_OFF   82432                   // 4 x 32768
#define SMEM_BYTES 213504

__device__ __forceinline__ void mma16816(float* c, const uint32_t* a,
                                         uint32_t b0, uint32_t b1) {
    asm volatile(
        "mma.sync.aligned.m16n8k16.row.col.f32.f16.f16.f32 "
        "{%0,%1,%2,%3}, {%4,%5,%6,%7}, {%8,%9}, {%0,%1,%2,%3};"
        : "+f"(c[0]), "+f"(c[1]), "+f"(c[2]), "+f"(c[3])
        : "r"(a[0]), "r"(a[1]), "r"(a[2]), "r"(a[3]), "r"(b0), "r"(b1));
}

__global__ __launch_bounds__(256, 1) void mma_kernel(const float* __restrict__ x,
                                                     const float* __restrict__ key,
                                                     const float* __restrict__ sens,
                                                     const float* __restrict__ keys_map,
                                                     float* __restrict__ out)
{
    extern __shared__ __align__(16) unsigned char sm[];
    float* simS = (float*)(sm + SIM_OFF);    // [row][m] stride 33

    uint32_t smb;
    asm("{ .reg .u64 t; cvta.to.shared.u64 t, %1; cvt.u32.u64 %0, t; }"
        : "=r"(smb) : "l"(sm));
    uint64_t gb;
    {
        const unsigned char* p = g_Bf;
        asm("cvta.to.global.u64 %0, %1;" : "=l"(gb) : "l"(p));
    }

    const int tid = threadIdx.x;
    const int l = tid & 31, w = tid >> 5;
    const int g = l >> 2, t = l & 3;
    const int rb = w;                                // A-build rowblock (0..7)
    const int rg = w >> 1, cg = w & 1;               // MMA mapping (32x64 tile)
    const int r0 = rb * 16 + g, r1 = r0 + 8;
    const int row0 = blockIdx.x * TB;

    // ---- issue cp.async for B chunks 0..2 (3 groups) ----
    #pragma unroll
    for (int cc = 0; cc < 3; cc++) {
        const uint32_t dst = smb + B_OFF + cc * 32768;
        const uint64_t src = gb + (uint64_t)cc * CHB;
        #pragma unroll
        for (int j = 0; j < 8; j++) {
            const uint32_t off = (uint32_t)(j * 256 + tid) * 16;
            asm volatile("cp.async.cg.shared.global [%0], [%1], 16;"
                         :: "r"(dst + off), "l"(src + off));
        }
        asm volatile("cp.async.commit_group;");
    }

    // ---- load this thread's 64 x-values straight to registers ----
    float xr[64];
    {
        const float* x0 = x + (size_t)(row0 + r0) * ND;
        const float* x1 = x + (size_t)(row0 + r1) * ND;
        #pragma unroll
        for (int j = 0; j < 8; j++) {
            const int k0 = j * 16 + 2 * t;
            float2 v;
            v = __ldg((const float2*)(x0 + k0));     xr[j*8+0] = v.x; xr[j*8+1] = v.y;
            v = __ldg((const float2*)(x0 + k0 + 8)); xr[j*8+2] = v.x; xr[j*8+3] = v.y;
            v = __ldg((const float2*)(x1 + k0));     xr[j*8+4] = v.x; xr[j*8+5] = v.y;
            v = __ldg((const float2*)(x1 + k0 + 8)); xr[j*8+6] = v.x; xr[j*8+7] = v.y;
        }
    }

    // ---- compute sim for this CTA's 128 rows (uses A-region SMEM as scratch) ----
    {
        float* kmS = (float*)(sm + A_OFF);           // [32][65] = 8320 B
        float* ksS = kmS + 32 * 65;                  // [128][64] = 32768 B
        float* ssS = ksS + 128 * 64;                 // [32]
        for (int i = tid; i < NM * NKEY; i += 256)
            kmS[(i >> 6) * 65 + (i & 63)] = keys_map[i];
        for (int i = tid; i < TB * NKEY; i += 256)
            ksS[i] = key[(size_t)row0 * NKEY + i];
        if (tid < NM) ssS[tid] = sens[tid];
        __syncthreads();

        const int m = l;
        #pragma unroll 1
        for (int i = 0; i < 16; i++) {
            const int r = w * 16 + i;
            float d2 = 0.f;
            #pragma unroll
            for (int k = 0; k < NKEY; k++) {
                const float df = ksS[r * 64 + k] - kmS[m * 65 + k];
                d2 = fmaf(df, df, d2);
            }
            const float lg = ssS[m] / (sqrtf(d2) + 1.0f);
            float mx = lg;
            #pragma unroll
            for (int o = 16; o > 0; o >>= 1)
                mx = fmaxf(mx, __shfl_xor_sync(0xFFFFFFFFu, mx, o));
            const float e = __expf(lg - mx);
            float s = e;
            #pragma unroll
            for (int o = 16; o > 0; o >>= 1)
                s += __shfl_xor_sync(0xFFFFFFFFu, s, o);
            simS[r * 33 + m] = e / s;
        }
        __syncthreads();    // sim done; A-region scratch dead
    }

    // ---- A-tile builder: thread owns rowblock rb, all 8 ksteps ----
    auto build_a = [&](int ch, unsigned char* dst) {
        if (ch < 32) {
            const float s0 = simS[r0 * 33 + ch];
            const float s1 = simS[r1 * 33 + ch];
            #pragma unroll
            for (int j = 0; j < 8; j++) {
                __half2 h0 = __floats2half2_rn(s0 * xr[j*8+0], s0 * xr[j*8+1]);
                __half2 h1 = __floats2half2_rn(s1 * xr[j*8+4], s1 * xr[j*8+5]);
                __half2 h2 = __floats2half2_rn(s0 * xr[j*8+2], s0 * xr[j*8+3]);
                __half2 h3 = __floats2half2_rn(s1 * xr[j*8+6], s1 * xr[j*8+7]);
                uint4 frag;
                frag.x = *(uint32_t*)&h0; frag.y = *(uint32_t*)&h1;
                frag.z = *(uint32_t*)&h2; frag.w = *(uint32_t*)&h3;
                *(uint4*)(dst + (size_t)((rb * 8 + j) * 32 + l) * 16) = frag;
            }
        } else {
            #pragma unroll
            for (int j = 0; j < 8; j++) {
                uint4 frag;
                if (j < 2) {               // bias chunk: A = sim over k<32
                    const int k0 = j * 16 + 2 * t;
                    __half2 h0 = __floats2half2_rn(simS[r0*33 + k0], simS[r0*33 + k0+1]);
                    __half2 h1 = __floats2half2_rn(simS[r1*33 + k0], simS[r1*33 + k0+1]);
                    __half2 h2 = __floats2half2_rn(simS[r0*33 + k0+8], simS[r0*33 + k0+9]);
                    __half2 h3 = __floats2half2_rn(simS[r1*33 + k0+8], simS[r1*33 + k0+9]);
                    frag.x = *(uint32_t*)&h0; frag.y = *(uint32_t*)&h1;
                    frag.z = *(uint32_t*)&h2; frag.w = *(uint32_t*)&h3;
                } else {
                    frag.x = frag.y = frag.z = frag.w = 0u;
                }
                *(uint4*)(dst + (size_t)((rb * 8 + j) * 32 + l) * 16) = frag;
            }
        }
    };

    build_a(0, sm + A_OFF);
    asm volatile("cp.async.wait_group 2;");
    __syncthreads();

    float acc[2][8][4];
    #pragma unroll
    for (int mf = 0; mf < 2; mf++)
        #pragma unroll
        for (int nf = 0; nf < 8; nf++)
            #pragma unroll
            for (int i = 0; i < 4; i++) acc[mf][nf][i] = 0.f;

    for (int c = 0; c < NCH; c++) {
        // prefetch B chunk c+3 into stage (c+3)%4
        if (c + 3 < NCH) {
            const uint32_t dst = smb + B_OFF + ((c + 3) & 3) * 32768;
            const uint64_t src = gb + (uint64_t)(c + 3) * CHB;
            #pragma unroll
            for (int j = 0; j < 8; j++) {
                const uint32_t off = (uint32_t)(j * 256 + tid) * 16;
                asm volatile("cp.async.cg.shared.global [%0], [%1], 16;"
                             :: "r"(dst + off), "l"(src + off));
            }
            asm volatile("cp.async.commit_group;");
        }

        // ---- MMA chunk c ----
        const uint4* aab = (const uint4*)(sm + A_OFF + (c & 1) * 32768);
        const uint4* bbb = (const uint4*)(sm + B_OFF + (c & 3) * 32768);
        #pragma unroll
        for (int ksn = 0; ksn < 8; ksn++) {
            uint4 A0 = aab[((rg * 2 + 0) * 8 + ksn) * 32 + l];
            uint4 A1 = aab[((rg * 2 + 1) * 8 + ksn) * 32 + l];
            uint32_t a0[4] = {A0.x, A0.y, A0.z, A0.w};
            uint32_t a1[4] = {A1.x, A1.y, A1.z, A1.w};
            #pragma unroll
            for (int nf2 = 0; nf2 < 4; nf2++) {
                uint4 Bp = bbb[(ksn * 8 + cg * 4 + nf2) * 32 + l];
                mma16816(acc[0][2*nf2+0], a0, Bp.x, Bp.y);
                mma16816(acc[1][2*nf2+0], a1, Bp.x, Bp.y);
                mma16816(acc[0][2*nf2+1], a0, Bp.z, Bp.w);
                mma16816(acc[1][2*nf2+1], a1, Bp.z, Bp.w);
            }
        }

        if (c + 1 < NCH) build_a(c + 1, sm + A_OFF + ((c + 1) & 1) * 32768);

        // wait for B chunk c+1
        if (c <= 29)      { asm volatile("cp.async.wait_group 2;"); }
        else if (c == 30) { asm volatile("cp.async.wait_group 1;"); }
        else if (c == 31) { asm volatile("cp.async.wait_group 0;"); }
        __syncthreads();
    }

    // ---- epilogue: scale by 1/32, store ----
    const float sc = 1.0f / 32.0f;
    #pragma unroll
    for (int mf = 0; mf < 2; mf++) {
        const int r = row0 + rg * 32 + mf * 16 + g;
        #pragma unroll
        for (int nf = 0; nf < 8; nf++) {
            const int col = cg * 64 + nf * 8 + 2 * t;
            float2 v0, v1;
            v0.x = acc[mf][nf][0] * sc; v0.y = acc[mf][nf][1] * sc;
            v1.x = acc[mf][nf][2] * sc; v1.y = acc[mf][nf][3] * sc;
            *(float2*)&out[(size_t)r * NU + col] = v0;
            *(float2*)&out[(size_t)(r + 8) * NU + col] = v1;
        }
    }
}

// ---------------------------------------------------------------------------
extern "C" void kernel_launch(void* const* d_in, const int* in_sizes, int n_in,
                              void* d_out, int out_size)
{
    const float *key = 0, *x = 0, *sens = 0, *keys_map = 0, *kernels = 0, *biases = 0;
    for (int i = 0; i < n_in; i++) {
        switch (in_sizes[i]) {
            case NB * NKEY:    key      = (const float*)d_in[i]; break;
            case NB * ND:      x        = (const float*)d_in[i]; break;
            case NM:           sens     = (const float*)d_in[i]; break;
            case NM * NKEY:    keys_map = (const float*)d_in[i]; break;
            case NM * ND * NU: kernels  = (const float*)d_in[i]; break;
            case NM * NU:      biases   = (const float*)d_in[i]; break;
            default: break;
        }
    }
    float* out = (float*)d_out;

    cudaFuncSetAttribute(mma_kernel, cudaFuncAttributeMaxDynamicSharedMemorySize,
                         SMEM_BYTES);

    prep_b<<<NCH * 4, 256>>>(kernels, biases);
    mma_kernel<<<NB / TB, 256, SMEM_BYTES>>>(x, key, sens, keys_map, out);
}

// round 6
// speedup vs baseline: 5.2827x; 1.0592x over previous
#include <cuda_runtime.h>
#include <cuda_fp16.h>
#include <cstdint>

#define NB 16384
#define NKEY 64
#define ND 128
#define NU 128
#define NM 32
#define TB 128
#define NCH 33            // 32 weight chunks (K=128) + 1 bias chunk (K=32, zero-padded)
#define CHB 32768         // bytes per fragment-ordered fp16 B chunk

__device__ __align__(16) unsigned char g_Bf[NCH * CHB];

// ---------------------------------------------------------------------------
// prep_b: B chunks -> fp16 fragment order, nf-paired uint4 layout, with the
// 1/MODES factor folded in. uint4 at ((ksn*8 + jp)*32 + l)*16 holds, for lane
// l {g=l>>2, t=l&3}, k0 = 16*ksn + 2*t, n_e = jp*16+g, n_o = n_e+8:
//   { h2(B[k0][n_e],B[k0+1][n_e]), h2(B[k0+8][n_e],B[k0+9][n_e]),
//     h2(B[k0][n_o],B[k0+1][n_o]), h2(B[k0+8][n_o],B[k0+9][n_o]) } * (1/32)
// c<32: B=kernels[c][k][n]; c==32: B=(k<32)?biases[k][n]:0.
// ---------------------------------------------------------------------------
__global__ __launch_bounds__(256) void prep_b(const float* __restrict__ kernels,
                                              const float* __restrict__ biases)
{
    __shared__ float Bs[32 * 129];
    const int pb = blockIdx.x;
    const int c = pb >> 2, p = pb & 3;
    const int tid = threadIdx.x;
    const float sc = 1.0f / 32.0f;

    for (int i = tid; i < 32 * 128; i += 256) {
        const int kl = i >> 7, n = i & 127, k = p * 32 + kl;
        float v;
        if (c < 32) v = kernels[(size_t)c * 16384 + (size_t)k * 128 + n];
        else        v = (p == 0) ? biases[k * 128 + n] : 0.f;
        Bs[kl * 129 + n] = v * sc;
    }
    __syncthreads();

    #pragma unroll
    for (int it = 0; it < 2; it++) {
        const int i = it * 256 + tid;               // 512 uint4 per part
        const int ksn = 2 * p + (i >> 8);
        const int rest = i & 255;
        const int jp = rest >> 5, l = rest & 31;
        const int g = l >> 2, t = l & 3;
        const int kl = 16 * (i >> 8) + 2 * t;       // local k within part
        const int ne = jp * 16 + g, no = ne + 8;
        __half2 h0 = __floats2half2_rn(Bs[kl * 129 + ne], Bs[(kl + 1) * 129 + ne]);
        __half2 h1 = __floats2half2_rn(Bs[(kl + 8) * 129 + ne], Bs[(kl + 9) * 129 + ne]);
        __half2 h2v = __floats2half2_rn(Bs[kl * 129 + no], Bs[(kl + 1) * 129 + no]);
        __half2 h3 = __floats2half2_rn(Bs[(kl + 8) * 129 + no], Bs[(kl + 9) * 129 + no]);
        uint4 wv;
        wv.x = *(uint32_t*)&h0;  wv.y = *(uint32_t*)&h1;
        wv.z = *(uint32_t*)&h2v; wv.w = *(uint32_t*)&h3;
        *(uint4*)(g_Bf + (size_t)c * CHB +
                  (size_t)((ksn * 8 + jp) * 32 + l) * 16) = wv;
    }
}

// ---------------------------------------------------------------------------
// mma_kernel: 128 CTAs x 256 threads (8 warps, warp tile 32x64).
// A NEVER touches SMEM: x lives in registers as half2 in fragment slot order;
// per chunk, A fragments are built with 1 HMUL2 per slot (sim broadcast).
// B: 4-stage cp.async pipeline, nf-paired uint4 reads.
// ---------------------------------------------------------------------------
#define SIM_OFF 0                       // 128*33 f32 = 16896
#define KM_OFF  16896                   // 32*65 f32 + sens = 8448
#define B_OFF   25344                   // 4 x 32768 = 131072
#define KS_OFF  (B_OFF + 3 * 32768)     // sim scratch inside B stage 3
#define SMEM_BYTES 156416

__device__ __forceinline__ void mma16816(float* c, const uint32_t* a,
                                         uint32_t b0, uint32_t b1) {
    asm volatile(
        "mma.sync.aligned.m16n8k16.row.col.f32.f16.f16.f32 "
        "{%0,%1,%2,%3}, {%4,%5,%6,%7}, {%8,%9}, {%0,%1,%2,%3};"
        : "+f"(c[0]), "+f"(c[1]), "+f"(c[2]), "+f"(c[3])
        : "r"(a[0]), "r"(a[1]), "r"(a[2]), "r"(a[3]), "r"(b0), "r"(b1));
}

__global__ __launch_bounds__(256, 1) void mma_kernel(const float* __restrict__ x,
                                                     const float* __restrict__ key,
                                                     const float* __restrict__ sens,
                                                     const float* __restrict__ keys_map,
                                                     float* __restrict__ out)
{
    extern __shared__ __align__(16) unsigned char sm[];
    float* simS = (float*)(sm + SIM_OFF);    // [row][m] stride 33

    uint32_t smb;
    asm("{ .reg .u64 t; cvta.to.shared.u64 t, %1; cvt.u32.u64 %0, t; }"
        : "=r"(smb) : "l"(sm));
    uint64_t gb;
    {
        const unsigned char* p = g_Bf;
        asm("cvta.to.global.u64 %0, %1;" : "=l"(gb) : "l"(p));
    }

    const int tid = threadIdx.x;
    const int l = tid & 31, w = tid >> 5;
    const int g = l >> 2, t = l & 3;
    const int rg = w >> 1, cg = w & 1;               // warp tile 32x64
    const int row0 = blockIdx.x * TB;
    const int r00 = rg * 32 + g;                     // this thread's 4 A rows
    const int r01 = r00 + 8, r10 = r00 + 16, r11 = r00 + 24;

    // ---- cp.async B chunks 0..2 ----
    #pragma unroll
    for (int cc = 0; cc < 3; cc++) {
        const uint32_t dst = smb + B_OFF + cc * 32768;
        const uint64_t src = gb + (uint64_t)cc * CHB;
        #pragma unroll
        for (int j = 0; j < 8; j++) {
            const uint32_t off = (uint32_t)(j * 256 + tid) * 16;
            asm volatile("cp.async.cg.shared.global [%0], [%1], 16;"
                         :: "r"(dst + off), "l"(src + off));
        }
        asm volatile("cp.async.commit_group;");
    }

    // ---- x -> registers as half2, fragment slot order ----
    __half2 xh[4][8][2];
    {
        const int rows[4] = {r00, r01, r10, r11};
        #pragma unroll
        for (int i = 0; i < 4; i++) {
            const float* xp = x + (size_t)(row0 + rows[i]) * ND;
            #pragma unroll
            for (int j = 0; j < 8; j++) {
                const int k0 = j * 16 + 2 * t;
                float2 v0 = __ldg((const float2*)(xp + k0));
                float2 v1 = __ldg((const float2*)(xp + k0 + 8));
                xh[i][j][0] = __floats2half2_rn(v0.x, v0.y);
                xh[i][j][1] = __floats2half2_rn(v1.x, v1.y);
            }
        }
    }

    // ---- compute sim for this CTA's 128 rows ----
    {
        float* kmS = (float*)(sm + KM_OFF);          // [32][65]
        float* ssS = kmS + 32 * 65;                  // [32]
        float* ksS = (float*)(sm + KS_OFF);          // [128][64] (B stage 3)
        for (int i = tid; i < NM * NKEY; i += 256)
            kmS[(i >> 6) * 65 + (i & 63)] = keys_map[i];
        for (int i = tid; i < TB * NKEY; i += 256)
            ksS[i] = key[(size_t)row0 * NKEY + i];
        if (tid < NM) ssS[tid] = sens[tid];
        __syncthreads();

        const int m = l;
        #pragma unroll 1
        for (int i = 0; i < 16; i++) {
            const int r = w * 16 + i;
            float d2 = 0.f;
            #pragma unroll
            for (int k = 0; k < NKEY; k++) {
                const float df = ksS[r * 64 + k] - kmS[m * 65 + k];
                d2 = fmaf(df, df, d2);
            }
            const float lg = ssS[m] / (sqrtf(d2) + 1.0f);
            float mx = lg;
            #pragma unroll
            for (int o = 16; o > 0; o >>= 1)
                mx = fmaxf(mx, __shfl_xor_sync(0xFFFFFFFFu, mx, o));
            const float e = __expf(lg - mx);
            float s = e;
            #pragma unroll
            for (int o = 16; o > 0; o >>= 1)
                s += __shfl_xor_sync(0xFFFFFFFFu, s, o);
            simS[r * 33 + m] = e / s;
        }
        __syncthreads();    // sim ready; ksS (B stage 3) dead
    }

    float acc[2][8][4];
    #pragma unroll
    for (int mf = 0; mf < 2; mf++)
        #pragma unroll
        for (int nf = 0; nf < 8; nf++)
            #pragma unroll
            for (int i = 0; i < 4; i++) acc[mf][nf][i] = 0.f;

    // ---- mainloop over the 32 weight chunks ----
    #pragma unroll 1
    for (int c = 0; c < 32; c++) {
        if (c < 30) {   // prefetch chunk c+3 into stage (c+3)&3
            const uint32_t dst = smb + B_OFF + ((c + 3) & 3) * 32768;
            const uint64_t src = gb + (uint64_t)(c + 3) * CHB;
            #pragma unroll
            for (int j = 0; j < 8; j++) {
                const uint32_t off = (uint32_t)(j * 256 + tid) * 16;
                asm volatile("cp.async.cg.shared.global [%0], [%1], 16;"
                             :: "r"(dst + off), "l"(src + off));
            }
            asm volatile("cp.async.commit_group;");
        }

        const __half2 sh0 = __float2half2_rn(simS[r00 * 33 + c]);
        const __half2 sh1 = __float2half2_rn(simS[r01 * 33 + c]);
        const __half2 sh2 = __float2half2_rn(simS[r10 * 33 + c]);
        const __half2 sh3 = __float2half2_rn(simS[r11 * 33 + c]);

        const uint4* bbb = (const uint4*)(sm + B_OFF + (c & 3) * 32768);
        #pragma unroll
        for (int ksn = 0; ksn < 8; ksn++) {
            __half2 f;
            uint32_t a0[4], a1[4];
            f = __hmul2(sh0, xh[0][ksn][0]); a0[0] = *(uint32_t*)&f;
            f = __hmul2(sh1, xh[1][ksn][0]); a0[1] = *(uint32_t*)&f;
            f = __hmul2(sh0, xh[0][ksn][1]); a0[2] = *(uint32_t*)&f;
            f = __hmul2(sh1, xh[1][ksn][1]); a0[3] = *(uint32_t*)&f;
            f = __hmul2(sh2, xh[2][ksn][0]); a1[0] = *(uint32_t*)&f;
            f = __hmul2(sh3, xh[3][ksn][0]); a1[1] = *(uint32_t*)&f;
            f = __hmul2(sh2, xh[2][ksn][1]); a1[2] = *(uint32_t*)&f;
            f = __hmul2(sh3, xh[3][ksn][1]); a1[3] = *(uint32_t*)&f;
            #pragma unroll
            for (int nf2 = 0; nf2 < 4; nf2++) {
                uint4 Bp = bbb[(ksn * 8 + cg * 4 + nf2) * 32 + l];
                mma16816(acc[0][2*nf2+0], a0, Bp.x, Bp.y);
                mma16816(acc[1][2*nf2+0], a1, Bp.x, Bp.y);
                mma16816(acc[0][2*nf2+1], a0, Bp.z, Bp.w);
                mma16816(acc[1][2*nf2+1], a1, Bp.z, Bp.w);
            }
        }

        // wait for chunk c+1; barrier protects B stage recycling
        if (c <= 29)      { asm volatile("cp.async.wait_group 2;"); }
        else              { asm volatile("cp.async.wait_group 0;"); }
        __syncthreads();
    }

    // ---- peeled bias chunk (c=32, B stage 0): A = sim over k<32 ----
    {
        const uint4* bbb = (const uint4*)(sm + B_OFF + 0 * 32768);
        #pragma unroll
        for (int ksn = 0; ksn < 2; ksn++) {
            const int k0 = ksn * 16 + 2 * t;
            __half2 f;
            uint32_t a0[4], a1[4];
            f = __floats2half2_rn(simS[r00*33 + k0], simS[r00*33 + k0+1]); a0[0] = *(uint32_t*)&f;
            f = __floats2half2_rn(simS[r01*33 + k0], simS[r01*33 + k0+1]); a0[1] = *(uint32_t*)&f;
            f = __floats2half2_rn(simS[r00*33 + k0+8], simS[r00*33 + k0+9]); a0[2] = *(uint32_t*)&f;
            f = __floats2half2_rn(simS[r01*33 + k0+8], simS[r01*33 + k0+9]); a0[3] = *(uint32_t*)&f;
            f = __floats2half2_rn(simS[r10*33 + k0], simS[r10*33 + k0+1]); a1[0] = *(uint32_t*)&f;
            f = __floats2half2_rn(simS[r11*33 + k0], simS[r11*33 + k0+1]); a1[1] = *(uint32_t*)&f;
            f = __floats2half2_rn(simS[r10*33 + k0+8], simS[r10*33 + k0+9]); a1[2] = *(uint32_t*)&f;
            f = __floats2half2_rn(simS[r11*33 + k0+8], simS[r11*33 + k0+9]); a1[3] = *(uint32_t*)&f;
            #pragma unroll
            for (int nf2 = 0; nf2 < 4; nf2++) {
                uint4 Bp = bbb[(ksn * 8 + cg * 4 + nf2) * 32 + l];
                mma16816(acc[0][2*nf2+0], a0, Bp.x, Bp.y);
                mma16816(acc[1][2*nf2+0], a1, Bp.x, Bp.y);
                mma16816(acc[0][2*nf2+1], a0, Bp.z, Bp.w);
                mma16816(acc[1][2*nf2+1], a1, Bp.z, Bp.w);
            }
        }
    }

    // ---- epilogue (1/32 already folded into B) ----
    #pragma unroll
    for (int mf = 0; mf < 2; mf++) {
        const int r = row0 + rg * 32 + mf * 16 + g;
        #pragma unroll
        for (int nf = 0; nf < 8; nf++) {
            const int col = cg * 64 + nf * 8 + 2 * t;
            float2 v0, v1;
            v0.x = acc[mf][nf][0]; v0.y = acc[mf][nf][1];
            v1.x = acc[mf][nf][2]; v1.y = acc[mf][nf][3];
            *(float2*)&out[(size_t)r * NU + col] = v0;
            *(float2*)&out[(size_t)(r + 8) * NU + col] = v1;
        }
    }
}

// ---------------------------------------------------------------------------
extern "C" void kernel_launch(void* const* d_in, const int* in_sizes, int n_in,
                              void* d_out, int out_size)
{
    const float *key = 0, *x = 0, *sens = 0, *keys_map = 0, *kernels = 0, *biases = 0;
    for (int i = 0; i < n_in; i++) {
        switch (in_sizes[i]) {
            case NB * NKEY:    key      = (const float*)d_in[i]; break;
            case NB * ND:      x        = (const float*)d_in[i]; break;
            case NM:           sens     = (const float*)d_in[i]; break;
            case NM * NKEY:    keys_map = (const float*)d_in[i]; break;
            case NM * ND * NU: kernels  = (const float*)d_in[i]; break;
            case NM * NU:      biases   = (const float*)d_in[i]; break;
            default: break;
        }
    }
    float* out = (float*)d_out;

    cudaFuncSetAttribute(mma_kernel, cudaFuncAttributeMaxDynamicSharedMemorySize,
                         SMEM_BYTES);

    prep_b<<<NCH * 4, 256>>>(kernels, biases);
    mma_kernel<<<NB / TB, 256, SMEM_BYTES>>>(x, key, sens, keys_map, out);
}